// round 1
// baseline (speedup 1.0000x reference)
#include <cuda_runtime.h>
#include <cstdint>

// ---------------------------------------------------------------------------
// MPS_33930241638883: 20-qubit statevector, K=1.
// Key structure:
//  - each q-block of 15 two-local gates composes to one 4x4 unitary U on
//    wires (q,q+1); thetas are params[0,:15] for EVERY q -> same U for all q.
//  - starting from |0>, support after gate q is 2^(q+2) amplitudes.
//  - gates 11..18 act on wires 11..19 = index bits 8..0 only -> each aligned
//    512-group evolves independently, from just 2 nonzero inputs (j=0, j=256).
//    => out-group = Mx2 matrix (512x2, fixed) times (a,b).
// Kernel A (1 block): build U, evolve gates 0..10 in smem (sparse), build M.
// Kernel B (grid): out[n] = |M[j,0]*a + M[j,1]*b|^2.
// ---------------------------------------------------------------------------

__device__ float4 g_S1[2048];   // 4096 complex (a,b pairs per group), m = n>>8
__device__ float4 g_M[512];     // M[j] = (m0.re, m0.im, m1.re, m1.im)

__device__ __forceinline__ float2 cmul(float2 a, float2 b) {
    return make_float2(a.x * b.x - a.y * b.y, a.x * b.y + a.y * b.x);
}
__device__ __forceinline__ float2 cadd(float2 a, float2 b) {
    return make_float2(a.x + b.x, a.y + b.y);
}

// basis-change 2x2 for non-I paulis: X->RY(-pi/2), Y->RX(+pi/2), Z->I
__device__ __forceinline__ float2 basisB(int p, int i, int j) {
    const float C = 0.70710678118654752f;
    if (p == 1) {                       // RY(-pi/2) = [[C, C], [-C, C]]
        return make_float2((i == 1 && j == 0) ? -C : C, 0.f);
    } else if (p == 2) {                // RX(+pi/2) = [[C,-iC],[-iC,C]]
        return (i == j) ? make_float2(C, 0.f) : make_float2(0.f, -C);
    } else {                            // identity
        return (i == j) ? make_float2(1.f, 0.f) : make_float2(0.f, 0.f);
    }
}

// rotation 2x2: p=1 RX, p=2 RY, p=3 RZ; ch=cos(t/2), sh=sin(t/2)
__device__ __forceinline__ float2 rotR(int p, int i, int j, float ch, float sh) {
    if (p == 1) {                       // RX: [[c,-is],[-is,c]]
        return (i == j) ? make_float2(ch, 0.f) : make_float2(0.f, -sh);
    } else if (p == 2) {                // RY: [[c,-s],[s,c]]
        if (i == j) return make_float2(ch, 0.f);
        return (i == 0) ? make_float2(-sh, 0.f) : make_float2(sh, 0.f);
    } else {                            // RZ: diag(e^-it/2, e^it/2)
        if (i != j) return make_float2(0.f, 0.f);
        return (j == 0) ? make_float2(ch, -sh) : make_float2(ch, sh);
    }
}

__device__ __forceinline__ void mat4vec(const float2* u,
                                        float2& v0, float2& v1,
                                        float2& v2, float2& v3) {
    float2 a0 = cadd(cadd(cmul(u[0],  v0), cmul(u[1],  v1)),
                     cadd(cmul(u[2],  v2), cmul(u[3],  v3)));
    float2 a1 = cadd(cadd(cmul(u[4],  v0), cmul(u[5],  v1)),
                     cadd(cmul(u[6],  v2), cmul(u[7],  v3)));
    float2 a2 = cadd(cadd(cmul(u[8],  v0), cmul(u[9],  v1)),
                     cadd(cmul(u[10], v2), cmul(u[11], v3)));
    float2 a3 = cadd(cadd(cmul(u[12], v0), cmul(u[13], v1)),
                     cadd(cmul(u[14], v2), cmul(u[15], v3)));
    v0 = a0; v1 = a1; v2 = a2; v3 = a3;
}

__global__ void __launch_bounds__(256, 1) stage1_kernel(const float* __restrict__ params) {
    __shared__ float2 s1[4096];     // state for gates 0..10 (m-space, n = m<<8)
    __shared__ float2 vm[1024];     // [j*2 + col], 512-dim x 2 columns
    __shared__ float2 sU[16], sG[16], sP[16];

    const int tid = threadIdx.x;

    // ---- Phase 0: build U (lanes 0..15, one matrix element each) ----
    if (tid < 16) {
        const int r = tid >> 2, c = tid & 3;
        const int ar = r >> 1, br = r & 1, ac = c >> 1, bc = c & 1;
        // pauli codes: first char = wire q (HIGH bit), second = wire q+1 (LOW)
        const int P0[15] = {0,0,0,1,1,1,1,2,2,2,2,3,3,3,3};
        const int P1[15] = {1,2,3,0,1,2,3,0,1,2,3,0,1,2,3};

        sU[tid] = (r == c) ? make_float2(1.f, 0.f) : make_float2(0.f, 0.f);
        __syncwarp(0xffffu);

        for (int i = 0; i < 15; i++) {
            float th = params[i];
            float ch = cosf(0.5f * th);
            float sh = sinf(0.5f * th);
            int p0 = P0[i], p1 = P1[i];
            float2 g;
            if (p0 == 0 || p1 == 0) {
                // single rotation (kron with identity)
                if (p1 == 0) {  // rotation on high wire: G = R (x) I
                    g = (br == bc) ? rotR(p0, ar, ac, ch, sh)
                                   : make_float2(0.f, 0.f);
                } else {        // rotation on low wire: G = I (x) R
                    g = (ar == ac) ? rotR(p1, br, bc, ch, sh)
                                   : make_float2(0.f, 0.f);
                }
            } else {
                // G = pre * D * pre, D = diag(d0,d1,d1,d0), d0=e^{-it/2}
                sP[tid] = cmul(basisB(p0, ar, ac), basisB(p1, br, bc));
                __syncwarp(0xffffu);
                float2 D[4];
                D[0] = make_float2(ch, -sh); D[1] = make_float2(ch,  sh);
                D[2] = make_float2(ch,  sh); D[3] = make_float2(ch, -sh);
                float2 acc = make_float2(0.f, 0.f);
                #pragma unroll
                for (int k = 0; k < 4; k++)
                    acc = cadd(acc, cmul(cmul(sP[r * 4 + k], D[k]), sP[k * 4 + c]));
                g = acc;
            }
            sG[tid] = g;
            __syncwarp(0xffffu);
            float2 acc = make_float2(0.f, 0.f);
            #pragma unroll
            for (int k = 0; k < 4; k++)
                acc = cadd(acc, cmul(sG[r * 4 + k], sU[k * 4 + c]));
            __syncwarp(0xffffu);
            sU[tid] = acc;      // U <- G * U
            __syncwarp(0xffffu);
        }
    }
    __syncthreads();

    // all threads: copy U to registers
    float2 u[16];
    #pragma unroll
    for (int k = 0; k < 16; k++) u[k] = sU[k];

    // ---- Phase 1: evolve gates 0..10 in m-space (wire w <-> m bit 11-w) ----
    for (int i = tid; i < 4096; i += 256)
        s1[i] = (i == 0) ? make_float2(1.f, 0.f) : make_float2(0.f, 0.f);
    __syncthreads();

    for (int q = 0; q <= 10; q++) {
        const int nb = 1 << q;          // only quads with nonzero support
        const int s  = 1 << (10 - q);
        for (int t = tid; t < nb; t += 256) {
            const int b = t << (12 - q);
            float2 v0 = s1[b], v1 = s1[b + s], v2 = s1[b + 2 * s], v3 = s1[b + 3 * s];
            mat4vec(u, v0, v1, v2, v3);
            s1[b] = v0; s1[b + s] = v1; s1[b + 2 * s] = v2; s1[b + 3 * s] = v3;
        }
        __syncthreads();
    }

    // write S1 as float4 (a,b) pairs per group: g_S1[g] = (s1[2g], s1[2g+1])
    for (int i = tid; i < 2048; i += 256) {
        float2 a = s1[2 * i], b = s1[2 * i + 1];
        g_S1[i] = make_float4(a.x, a.y, b.x, b.y);
    }

    // ---- Phase 2: build M = gates 11..18 applied to e_0 and e_256 ----
    for (int i = tid; i < 1024; i += 256) vm[i] = make_float2(0.f, 0.f);
    __syncthreads();
    if (tid == 0) {
        vm[0 * 2 + 0]   = make_float2(1.f, 0.f);   // column 0: j=0 input
        vm[256 * 2 + 1] = make_float2(1.f, 0.f);   // column 1: j=256 input
    }
    __syncthreads();

    for (int q = 11; q <= 18; q++) {
        const int lg = 18 - q;
        const int s  = 1 << lg;
        for (int t = tid; t < 128; t += 256) {
            const int b = (t & (s - 1)) | ((t >> lg) << (lg + 2));
            #pragma unroll
            for (int col = 0; col < 2; col++) {
                float2 v0 = vm[(b)         * 2 + col];
                float2 v1 = vm[(b + s)     * 2 + col];
                float2 v2 = vm[(b + 2 * s) * 2 + col];
                float2 v3 = vm[(b + 3 * s) * 2 + col];
                mat4vec(u, v0, v1, v2, v3);
                vm[(b)         * 2 + col] = v0;
                vm[(b + s)     * 2 + col] = v1;
                vm[(b + 2 * s) * 2 + col] = v2;
                vm[(b + 3 * s) * 2 + col] = v3;
            }
        }
        __syncthreads();
    }

    for (int j = tid; j < 512; j += 256) {
        float2 m0 = vm[j * 2], m1 = vm[j * 2 + 1];
        g_M[j] = make_float4(m0.x, m0.y, m1.x, m1.y);
    }
}

__global__ void __launch_bounds__(256, 8) stage2_kernel(float* __restrict__ out) {
    const int n = blockIdx.x * 256 + threadIdx.x;
    const int j = n & 511;
    const int g = n >> 9;
    const float4 mm = g_M[j];     // coalesced 16B/thread
    const float4 ab = g_S1[g];    // broadcast within 512-thread group
    // c = m0*a + m1*b ; out = |c|^2
    const float cr = mm.x * ab.x - mm.y * ab.y + mm.z * ab.z - mm.w * ab.w;
    const float ci = mm.x * ab.y + mm.y * ab.x + mm.z * ab.w + mm.w * ab.z;
    out[n] = cr * cr + ci * ci;
}

extern "C" void kernel_launch(void* const* d_in, const int* in_sizes, int n_in,
                              void* d_out, int out_size) {
    const float* params = (const float*)d_in[0];
    float* out = (float*)d_out;
    stage1_kernel<<<1, 256>>>(params);
    stage2_kernel<<<(1 << 20) / 256, 256>>>(out);
}